// round 1
// baseline (speedup 1.0000x reference)
#include <cuda_runtime.h>
#include <cstdint>

// Problem constants
#define DD   4096
#define OBJN 20
#define MCNT 1000
#define FR   20
#define BB   4
#define QQ   4
#define NROWS 32      // compacted rows: 16 high + 16 low
#define KSPLIT 8

#define RP_ELEMS 26214400ull          // Q*B*F*OBJ*D
#define OUT_HIGH (2ull*RP_ELEMS)      // 52428800
#define OUT_LOW  (2ull*RP_ELEMS + 16ull)

// ---------------- scratch (device globals; no allocation allowed) ----------
__device__ int   g_high[16];
__device__ int   g_low[16];
__device__ int   g_rowbf[32];                 // compact row -> b*20+f
__device__ float g_invn[BB*FR*OBJN];          // per-region inverse norms
__device__ float g_Rmax[BB*FR*DD];            // normalized max-pooled input rows
__device__ float g_memmp[2*MCNT*DD];          // normalized max-pooled mem rows
__device__ float g_part[KSPLIT*2*NROWS*1024]; // k-split partial scores
__device__ int   g_sim[64];                   // [sel][32] argmax results

// ---------------- helpers ---------------------------------------------------
__device__ __forceinline__ float blockReduceSum256(float v, float* sh) {
    #pragma unroll
    for (int o = 16; o > 0; o >>= 1) v += __shfl_xor_sync(0xffffffffu, v, o);
    int lane = threadIdx.x & 31, w = threadIdx.x >> 5;
    if (lane == 0) sh[w] = v;
    __syncthreads();
    if (threadIdx.x < 32) {
        float r = (threadIdx.x < 8) ? sh[threadIdx.x] : 0.f;
        #pragma unroll
        for (int o = 4; o > 0; o >>= 1) r += __shfl_xor_sync(0xffffffffu, r, o);
        if (threadIdx.x == 0) sh[0] = r;
    }
    __syncthreads();
    float res = sh[0];
    __syncthreads();
    return res;
}

// ---------------- K1: top-k / rank-selected indices -------------------------
__global__ void k_idx(const float* __restrict__ qr, const int* __restrict__ rnd) {
    int t = threadIdx.x;
    if (t < 16) {
        int b = t >> 2;
        const float* v = qr + t * FR;   // [B,Q,F], t=b*Q+q
        int hi = 0; float hv = v[0];
        for (int i = 1; i < FR; i++) { float x = v[i]; if (x > hv) { hv = x; hi = i; } }
        int r = rnd[t];
        int lo = 0;
        for (int i = 0; i < FR; i++) {
            int rank = 0;
            float c = v[i];
            for (int j = 0; j < FR; j++) {
                float a = v[j];
                rank += (a < c) || (a == c && j < i);
            }
            if (rank == r) { lo = i; break; }
        }
        g_high[t] = hi;
        g_low[t]  = lo;
        g_rowbf[t]      = b * FR + hi;   // compact rows 0..15 : high
        g_rowbf[16 + t] = b * FR + lo;   // compact rows 16..31: low
    }
}

// ---------------- K2: per-region inv norms + normalized maxpool of input ----
__global__ void __launch_bounds__(256) k_rmax(const float* __restrict__ inp) {
    int bf = blockIdx.x;             // b*20+f, 80 blocks
    int t  = threadIdx.x;
    __shared__ float sh[32];
    __shared__ float s_inv[OBJN];
    const float* base = inp + (size_t)bf * (OBJN * DD);

    for (int o = 0; o < OBJN; o++) {
        const float4* p = (const float4*)(base + o * DD);
        float s = 0.f;
        #pragma unroll
        for (int i = 0; i < 4; i++) {
            float4 v = __ldg(p + t + i * 256);
            s += v.x*v.x + v.y*v.y + v.z*v.z + v.w*v.w;
        }
        float tot = blockReduceSum256(s, sh);
        if (t == 0) s_inv[o] = 1.0f / fmaxf(sqrtf(tot), 1e-12f);
    }
    __syncthreads();
    if (t < OBJN) g_invn[bf * OBJN + t] = s_inv[t];

    float4 mx[4];
    #pragma unroll
    for (int i = 0; i < 4; i++) mx[i] = make_float4(-3.4e38f, -3.4e38f, -3.4e38f, -3.4e38f);
    for (int o = 0; o < OBJN; o++) {
        float inv = s_inv[o];
        const float4* p = (const float4*)(base + o * DD);
        #pragma unroll
        for (int i = 0; i < 4; i++) {
            float4 v = __ldg(p + t + i * 256);
            mx[i].x = fmaxf(mx[i].x, v.x * inv);
            mx[i].y = fmaxf(mx[i].y, v.y * inv);
            mx[i].z = fmaxf(mx[i].z, v.z * inv);
            mx[i].w = fmaxf(mx[i].w, v.w * inv);
        }
    }
    float s = 0.f;
    #pragma unroll
    for (int i = 0; i < 4; i++) s += mx[i].x*mx[i].x + mx[i].y*mx[i].y + mx[i].z*mx[i].z + mx[i].w*mx[i].w;
    float tot = blockReduceSum256(s, sh);
    float inv2 = 1.0f / fmaxf(sqrtf(tot), 1e-12f);
    float4* op = (float4*)(g_Rmax + (size_t)bf * DD);
    #pragma unroll
    for (int i = 0; i < 4; i++) {
        float4 v = mx[i];
        v.x *= inv2; v.y *= inv2; v.z *= inv2; v.w *= inv2;
        op[t + i * 256] = v;
    }
}

// ---------------- K3: mem maxpool + normalize (dominant, 655 MB stream) -----
__global__ void __launch_bounds__(256) k_memmp(const float* __restrict__ mem1,
                                               const float* __restrict__ mem2) {
    int m = blockIdx.x, sel = blockIdx.y;
    const float* mem = sel ? mem2 : mem1;
    int t = threadIdx.x;
    __shared__ float sh[32];
    const float4* base = (const float4*)(mem + (size_t)m * (OBJN * DD));
    float4 mx[4];
    #pragma unroll
    for (int i = 0; i < 4; i++) mx[i] = make_float4(-3.4e38f, -3.4e38f, -3.4e38f, -3.4e38f);
    for (int o = 0; o < OBJN; o++) {
        const float4* p = base + o * (DD / 4);
        #pragma unroll
        for (int i = 0; i < 4; i++) {
            float4 v = __ldcs(p + t + i * 256);   // streaming: don't pollute L2
            mx[i].x = fmaxf(mx[i].x, v.x);
            mx[i].y = fmaxf(mx[i].y, v.y);
            mx[i].z = fmaxf(mx[i].z, v.z);
            mx[i].w = fmaxf(mx[i].w, v.w);
        }
    }
    float s = 0.f;
    #pragma unroll
    for (int i = 0; i < 4; i++) s += mx[i].x*mx[i].x + mx[i].y*mx[i].y + mx[i].z*mx[i].z + mx[i].w*mx[i].w;
    float tot = blockReduceSum256(s, sh);
    float inv = 1.0f / fmaxf(sqrtf(tot), 1e-12f);
    float4* op = (float4*)(g_memmp + ((size_t)sel * MCNT + m) * DD);
    #pragma unroll
    for (int i = 0; i < 4; i++) {
        float4 v = mx[i];
        v.x *= inv; v.y *= inv; v.z *= inv; v.w *= inv;
        op[t + i * 256] = v;
    }
}

// ---------------- K4: fp32 score GEMM (32 rows x 1000 mem x 4096 K), k-split -
__global__ void __launch_bounds__(256) k_scores() {
    int sel = blockIdx.z;
    int m0  = blockIdx.x * 128;
    int kb  = blockIdx.y * (DD / KSPLIT);   // 512-wide K segment
    int t   = threadIdx.x;
    __shared__ float Rs[NROWS][64];
    __shared__ float Ms[128][65];
    __shared__ int   rowbase[NROWS];
    if (t < NROWS) rowbase[t] = g_rowbf[t] * DD;

    float acc[4][4];
    #pragma unroll
    for (int i = 0; i < 4; i++)
        #pragma unroll
        for (int j = 0; j < 4; j++) acc[i][j] = 0.f;

    const float* memmp = g_memmp + (size_t)sel * MCNT * DD;
    int c  = t & 31;     // base col
    int rt = t >> 5;     // row group 0..7 -> rows rt*4 .. rt*4+3

    for (int kc = 0; kc < DD / KSPLIT; kc += 64) {
        __syncthreads();
        int k0 = kb + kc;
        for (int i = t; i < NROWS * 64; i += 256) {
            int r = i >> 6, k = i & 63;
            Rs[r][k] = g_Rmax[rowbase[r] + k0 + k];
        }
        for (int i = t; i < 128 * 64; i += 256) {
            int cc = i >> 6, k = i & 63;
            int m = m0 + cc;
            Ms[cc][k] = (m < MCNT) ? memmp[(size_t)m * DD + k0 + k] : 0.f;
        }
        __syncthreads();
        #pragma unroll 4
        for (int k = 0; k < 64; k++) {
            float rv[4], mv[4];
            #pragma unroll
            for (int j = 0; j < 4; j++) rv[j] = Rs[rt * 4 + j][k];
            #pragma unroll
            for (int j = 0; j < 4; j++) mv[j] = Ms[c + j * 32][k];
            #pragma unroll
            for (int i = 0; i < 4; i++)
                #pragma unroll
                for (int j = 0; j < 4; j++) acc[i][j] += rv[i] * mv[j];
        }
    }
    float* part = g_part + (((size_t)blockIdx.y * 2 + sel) * NROWS) * 1024;
    #pragma unroll
    for (int i = 0; i < 4; i++)
        #pragma unroll
        for (int j = 0; j < 4; j++) {
            int row = rt * 4 + i;
            int m   = m0 + c + j * 32;
            part[row * 1024 + m] = acc[i][j];
        }
}

// ---------------- K4b: deterministic reduce + argmax ------------------------
__global__ void __launch_bounds__(256) k_argmax() {
    int row = blockIdx.x;            // 0..63
    int sel = row >> 5, r = row & 31;
    int t = threadIdx.x;
    __shared__ unsigned long long sh[8];
    unsigned long long best = 0ull;
    for (int m = t; m < MCNT; m += 256) {
        float s = 0.f;
        #pragma unroll
        for (int ks = 0; ks < KSPLIT; ks++)
            s += g_part[(((size_t)ks * 2 + sel) * NROWS + r) * 1024 + m];
        unsigned u = __float_as_uint(s);
        u ^= (u >> 31) ? 0xFFFFFFFFu : 0x80000000u;
        unsigned long long pv = ((unsigned long long)u << 32) | (unsigned)(0xFFFFFFFFu - (unsigned)m);
        best = (pv > best) ? pv : best;
    }
    #pragma unroll
    for (int o = 16; o > 0; o >>= 1) {
        unsigned long long x = __shfl_xor_sync(0xffffffffu, best, o);
        best = (x > best) ? x : best;
    }
    if ((t & 31) == 0) sh[t >> 5] = best;
    __syncthreads();
    if (t == 0) {
        #pragma unroll
        for (int w = 1; w < 8; w++) best = (sh[w] > best) ? sh[w] : best;
        g_sim[sel * 32 + r] = (int)(0xFFFFFFFFu - (unsigned)(best & 0xFFFFFFFFu));
    }
}

// ---------------- K5: assemble Rp / Rn (210 MB writes) ----------------------
__global__ void __launch_bounds__(256) k_out(const float* __restrict__ inp,
                                             const float* __restrict__ mem1,
                                             const float* __restrict__ mem2,
                                             float* __restrict__ out) {
    int id = blockIdx.x;             // 0..319 == q*80 + b*20 + f
    int o  = blockIdx.y;             // 0..19
    int q  = id / 80;
    int rem = id - q * 80;
    int b  = rem / FR;
    int f  = rem - b * FR;
    int bq = b * QQ + q;
    int hi = g_high[bq], lo = g_low[bq];
    int t  = threadIdx.x;

    size_t outoff = ((size_t)id * OBJN + o) * DD;
    float4* op = (float4*)(out + outoff);                 // Rp
    float4* on = (float4*)(out + RP_ELEMS + outoff);      // Rn
    const float4* pr = (const float4*)(inp + (((size_t)(b * FR + f)) * OBJN + o) * DD);
    float invn = g_invn[(b * FR + f) * OBJN + o];

    if (f != hi && f != lo) {
        #pragma unroll
        for (int i = 0; i < 4; i++) {
            float4 v = __ldg(pr + t + i * 256);
            v.x *= invn; v.y *= invn; v.z *= invn; v.w *= invn;
            __stcs(op + t + i * 256, v);
            __stcs(on + t + i * 256, v);
        }
    } else if (f == hi) {
        // Rn <- mem2[sim2 @ low]; Rp <- R
        int s = g_sim[32 + 16 + bq];
        const float4* pm = (const float4*)(mem2 + (size_t)s * (OBJN * DD) + o * DD);
        #pragma unroll
        for (int i = 0; i < 4; i++) {
            float4 v = __ldg(pr + t + i * 256);
            v.x *= invn; v.y *= invn; v.z *= invn; v.w *= invn;
            __stcs(op + t + i * 256, v);
            float4 w = __ldg(pm + t + i * 256);
            __stcs(on + t + i * 256, w);
        }
    } else {
        // f == lo: Rp <- mem1[sim1 @ low]; Rn <- R
        int s = g_sim[16 + bq];
        const float4* pm = (const float4*)(mem1 + (size_t)s * (OBJN * DD) + o * DD);
        #pragma unroll
        for (int i = 0; i < 4; i++) {
            float4 w = __ldg(pm + t + i * 256);
            __stcs(op + t + i * 256, w);
            float4 v = __ldg(pr + t + i * 256);
            v.x *= invn; v.y *= invn; v.z *= invn; v.w *= invn;
            __stcs(on + t + i * 256, v);
        }
    }
}

// ---------------- K6: high_sim / low_sim outputs ----------------------------
__global__ void k_sims(float* __restrict__ out) {
    int t = threadIdx.x;
    if (t < 16) {
        int q = t >> 2, b = t & 3;
        int bq = b * QQ + q;
        out[OUT_HIGH + t] = (float)g_sim[32 + bq];       // sim2 at high row
        out[OUT_LOW  + t] = (float)g_sim[16 + bq];       // sim1 at low row
    }
}

// ---------------- launch -----------------------------------------------------
extern "C" void kernel_launch(void* const* d_in, const int* in_sizes, int n_in,
                              void* d_out, int out_size) {
    const float* qr   = (const float*)d_in[0];   // [4,4,20]
    const float* inp  = (const float*)d_in[1];   // [4,20,20,4096]
    const float* mem1 = (const float*)d_in[2];   // [1000,81920]
    const float* mem2 = (const float*)d_in[3];   // [1000,81920]
    const int*   rnd  = (const int*)d_in[4];     // [4,4,1]
    float* out = (float*)d_out;

    k_idx<<<1, 32>>>(qr, rnd);
    k_rmax<<<80, 256>>>(inp);
    k_memmp<<<dim3(MCNT, 2), 256>>>(mem1, mem2);
    k_scores<<<dim3(8, KSPLIT, 2), 256>>>();
    k_argmax<<<64, 256>>>();
    k_out<<<dim3(320, OBJN), 256>>>(inp, mem1, mem2, out);
    k_sims<<<1, 32>>>(out);
}

// round 2
// speedup vs baseline: 1.1447x; 1.1447x over previous
#include <cuda_runtime.h>
#include <cstdint>

// Problem constants
#define DD   4096
#define OBJN 20
#define MCNT 1000
#define FR   20
#define BB   4
#define QQ   4
#define NROWS 32      // compacted rows: 16 high + 16 low
#define KSPLIT 16

#define RP_ELEMS 26214400ull          // Q*B*F*OBJ*D
#define OUT_HIGH (2ull*RP_ELEMS)      // 52428800
#define OUT_LOW  (2ull*RP_ELEMS + 16ull)

typedef unsigned long long ull;

// ---------------- scratch (device globals; no allocation allowed) ----------
__device__ int   g_high[16];
__device__ int   g_low[16];
__device__ int   g_rowbf[32];                 // compact row -> b*20+f
__device__ float g_invn[BB*FR*OBJN];          // per-region inverse norms
__device__ float g_Rmax[BB*FR*DD];            // normalized max-pooled input rows
__device__ float g_memmp[2*MCNT*DD];          // normalized max-pooled mem rows
__device__ float g_part[KSPLIT*2*NROWS*1024]; // k-split partial scores
__device__ int   g_sim[64];                   // [sel][32] argmax results

// ---------------- helpers ---------------------------------------------------
__device__ __forceinline__ float blockReduceSum256(float v, float* sh) {
    #pragma unroll
    for (int o = 16; o > 0; o >>= 1) v += __shfl_xor_sync(0xffffffffu, v, o);
    int lane = threadIdx.x & 31, w = threadIdx.x >> 5;
    if (lane == 0) sh[w] = v;
    __syncthreads();
    if (threadIdx.x < 32) {
        float r = (threadIdx.x < 8) ? sh[threadIdx.x] : 0.f;
        #pragma unroll
        for (int o = 4; o > 0; o >>= 1) r += __shfl_xor_sync(0xffffffffu, r, o);
        if (threadIdx.x == 0) sh[0] = r;
    }
    __syncthreads();
    float res = sh[0];
    __syncthreads();
    return res;
}

// packed f32x2 FMA: d += a * b (elementwise on 2 packed floats)
__device__ __forceinline__ void ffma2(ull& d, ull a, ull b) {
    asm("fma.rn.f32x2 %0, %1, %2, %0;" : "+l"(d) : "l"(a), "l"(b));
}

// ---------------- K1: top-k / rank-selected indices -------------------------
__global__ void k_idx(const float* __restrict__ qr, const int* __restrict__ rnd) {
    int t = threadIdx.x;
    if (t < 16) {
        int b = t >> 2;
        const float* v = qr + t * FR;   // [B,Q,F], t=b*Q+q
        int hi = 0; float hv = v[0];
        for (int i = 1; i < FR; i++) { float x = v[i]; if (x > hv) { hv = x; hi = i; } }
        int r = rnd[t];
        int lo = 0;
        for (int i = 0; i < FR; i++) {
            int rank = 0;
            float c = v[i];
            for (int j = 0; j < FR; j++) {
                float a = v[j];
                rank += (a < c) || (a == c && j < i);
            }
            if (rank == r) { lo = i; break; }
        }
        g_high[t] = hi;
        g_low[t]  = lo;
        g_rowbf[t]      = b * FR + hi;   // compact rows 0..15 : high
        g_rowbf[16 + t] = b * FR + lo;   // compact rows 16..31: low
    }
}

// ---------------- K2: per-region inv norms + normalized maxpool of input ----
__global__ void __launch_bounds__(256) k_rmax(const float* __restrict__ inp) {
    int bf = blockIdx.x;             // b*20+f, 80 blocks
    int t  = threadIdx.x;
    __shared__ float sh[32];
    __shared__ float s_inv[OBJN];
    const float* base = inp + (size_t)bf * (OBJN * DD);

    for (int o = 0; o < OBJN; o++) {
        const float4* p = (const float4*)(base + o * DD);
        float s = 0.f;
        #pragma unroll
        for (int i = 0; i < 4; i++) {
            float4 v = __ldg(p + t + i * 256);
            s += v.x*v.x + v.y*v.y + v.z*v.z + v.w*v.w;
        }
        float tot = blockReduceSum256(s, sh);
        if (t == 0) s_inv[o] = 1.0f / fmaxf(sqrtf(tot), 1e-12f);
    }
    __syncthreads();
    if (t < OBJN) g_invn[bf * OBJN + t] = s_inv[t];

    float4 mx[4];
    #pragma unroll
    for (int i = 0; i < 4; i++) mx[i] = make_float4(-3.4e38f, -3.4e38f, -3.4e38f, -3.4e38f);
    for (int o = 0; o < OBJN; o++) {
        float inv = s_inv[o];
        const float4* p = (const float4*)(base + o * DD);
        #pragma unroll
        for (int i = 0; i < 4; i++) {
            float4 v = __ldg(p + t + i * 256);
            mx[i].x = fmaxf(mx[i].x, v.x * inv);
            mx[i].y = fmaxf(mx[i].y, v.y * inv);
            mx[i].z = fmaxf(mx[i].z, v.z * inv);
            mx[i].w = fmaxf(mx[i].w, v.w * inv);
        }
    }
    float s = 0.f;
    #pragma unroll
    for (int i = 0; i < 4; i++) s += mx[i].x*mx[i].x + mx[i].y*mx[i].y + mx[i].z*mx[i].z + mx[i].w*mx[i].w;
    float tot = blockReduceSum256(s, sh);
    float inv2 = 1.0f / fmaxf(sqrtf(tot), 1e-12f);
    float4* op = (float4*)(g_Rmax + (size_t)bf * DD);
    #pragma unroll
    for (int i = 0; i < 4; i++) {
        float4 v = mx[i];
        v.x *= inv2; v.y *= inv2; v.z *= inv2; v.w *= inv2;
        op[t + i * 256] = v;
    }
}

// ---------------- K3: mem maxpool + normalize (dominant, 655 MB stream) -----
__global__ void __launch_bounds__(256) k_memmp(const float* __restrict__ mem1,
                                               const float* __restrict__ mem2) {
    int m = blockIdx.x, sel = blockIdx.y;
    const float* mem = sel ? mem2 : mem1;
    int t = threadIdx.x;
    __shared__ float sh[32];
    const float4* base = (const float4*)(mem + (size_t)m * (OBJN * DD));
    float4 mx[4];
    #pragma unroll
    for (int i = 0; i < 4; i++) mx[i] = make_float4(-3.4e38f, -3.4e38f, -3.4e38f, -3.4e38f);
    for (int o = 0; o < OBJN; o++) {
        const float4* p = base + o * (DD / 4);
        #pragma unroll
        for (int i = 0; i < 4; i++) {
            float4 v = __ldcs(p + t + i * 256);   // streaming: don't pollute L2
            mx[i].x = fmaxf(mx[i].x, v.x);
            mx[i].y = fmaxf(mx[i].y, v.y);
            mx[i].z = fmaxf(mx[i].z, v.z);
            mx[i].w = fmaxf(mx[i].w, v.w);
        }
    }
    float s = 0.f;
    #pragma unroll
    for (int i = 0; i < 4; i++) s += mx[i].x*mx[i].x + mx[i].y*mx[i].y + mx[i].z*mx[i].z + mx[i].w*mx[i].w;
    float tot = blockReduceSum256(s, sh);
    float inv = 1.0f / fmaxf(sqrtf(tot), 1e-12f);
    float4* op = (float4*)(g_memmp + ((size_t)sel * MCNT + m) * DD);
    #pragma unroll
    for (int i = 0; i < 4; i++) {
        float4 v = mx[i];
        v.x *= inv; v.y *= inv; v.z *= inv; v.w *= inv;
        op[t + i * 256] = v;
    }
}

// ---------------- K4: fp32 score GEMM (32 x 1000 x 4096), f32x2, k-split ----
__global__ void __launch_bounds__(256) k_scores() {
    int sel = blockIdx.z;
    int m0  = blockIdx.x * 128;             // 8 m-tiles of 128
    int kb  = blockIdx.y * (DD / KSPLIT);   // 256-wide K segment
    int t   = threadIdx.x;
    __shared__ float Rs[NROWS][64];         // [row][k]  (row stride 64: f4-aligned)
    __shared__ float Ms[128][66];           // [col][k]  (pad 66: 8B-aligned, 2-way)
    __shared__ int   rowbase[NROWS];
    if (t < NROWS) rowbase[t] = g_rowbf[t] * DD;

    ull acc[4][4];
    #pragma unroll
    for (int i = 0; i < 4; i++)
        #pragma unroll
        for (int j = 0; j < 4; j++) acc[i][j] = 0ull;

    const float* memmp = g_memmp + (size_t)sel * MCNT * DD;
    int c  = t & 31;     // base col
    int rt = t >> 5;     // row group 0..7 -> rows rt*4 .. rt*4+3

    for (int kc = 0; kc < DD / KSPLIT; kc += 64) {   // 4 chunks of 64
        __syncthreads();
        int k0 = kb + kc;
        // Rs: 32 rows x 64 k  (2048 floats, 8/thread, coalesced along k)
        for (int i = t; i < NROWS * 64; i += 256) {
            int r = i >> 6, k = i & 63;
            Rs[r][k] = g_Rmax[rowbase[r] + k0 + k];
        }
        // Ms: 128 cols x 64 k via float4 global loads (coalesced)
        for (int i = t; i < 128 * 16; i += 256) {
            int cc = i >> 4, kq = (i & 15) << 2;     // kq = 0,4,...,60
            int m = m0 + cc;
            float4 v = (m < MCNT)
                ? __ldg((const float4*)(memmp + (size_t)m * DD + k0 + kq))
                : make_float4(0.f, 0.f, 0.f, 0.f);
            ull* w = (ull*)&Ms[cc][kq];              // 8B-aligned (66*cc even, kq even)
            ull w0, w1;
            asm("mov.b64 %0, {%1,%2};" : "=l"(w0) : "f"(v.x), "f"(v.y));
            asm("mov.b64 %0, {%1,%2};" : "=l"(w1) : "f"(v.z), "f"(v.w));
            w[0] = w0; w[1] = w1;
        }
        __syncthreads();
        #pragma unroll 8
        for (int k = 0; k < 64; k += 2) {
            ull rv[4], mv[4];
            #pragma unroll
            for (int i = 0; i < 4; i++) rv[i] = *(const ull*)&Rs[rt * 4 + i][k];
            #pragma unroll
            for (int j = 0; j < 4; j++) mv[j] = *(const ull*)&Ms[c + j * 32][k];
            #pragma unroll
            for (int i = 0; i < 4; i++)
                #pragma unroll
                for (int j = 0; j < 4; j++) ffma2(acc[i][j], rv[i], mv[j]);
        }
    }
    // lane reduce (deterministic: lo + hi) and partial store
    float* part = g_part + (((size_t)blockIdx.y * 2 + sel) * NROWS) * 1024;
    #pragma unroll
    for (int i = 0; i < 4; i++)
        #pragma unroll
        for (int j = 0; j < 4; j++) {
            unsigned lo, hi;
            asm("mov.b64 {%0,%1}, %2;" : "=r"(lo), "=r"(hi) : "l"(acc[i][j]));
            float s = __uint_as_float(lo) + __uint_as_float(hi);
            int row = rt * 4 + i;
            int m   = m0 + c + j * 32;
            part[row * 1024 + m] = s;
        }
}

// ---------------- K4b: deterministic reduce + argmax ------------------------
__global__ void __launch_bounds__(256) k_argmax() {
    int row = blockIdx.x;            // 0..63
    int sel = row >> 5, r = row & 31;
    int t = threadIdx.x;
    __shared__ unsigned long long sh[8];
    unsigned long long best = 0ull;
    for (int m = t; m < MCNT; m += 256) {
        float s = 0.f;
        #pragma unroll
        for (int ks = 0; ks < KSPLIT; ks++)
            s += g_part[(((size_t)ks * 2 + sel) * NROWS + r) * 1024 + m];
        unsigned u = __float_as_uint(s);
        u ^= (u >> 31) ? 0xFFFFFFFFu : 0x80000000u;
        unsigned long long pv = ((unsigned long long)u << 32) | (unsigned)(0xFFFFFFFFu - (unsigned)m);
        best = (pv > best) ? pv : best;
    }
    #pragma unroll
    for (int o = 16; o > 0; o >>= 1) {
        unsigned long long x = __shfl_xor_sync(0xffffffffu, best, o);
        best = (x > best) ? x : best;
    }
    if ((t & 31) == 0) sh[t >> 5] = best;
    __syncthreads();
    if (t == 0) {
        #pragma unroll
        for (int w = 1; w < 8; w++) best = (sh[w] > best) ? sh[w] : best;
        g_sim[sel * 32 + r] = (int)(0xFFFFFFFFu - (unsigned)(best & 0xFFFFFFFFu));
    }
}

// ---------------- K5: assemble Rp / Rn (210 MB writes) ----------------------
__global__ void __launch_bounds__(256) k_out(const float* __restrict__ inp,
                                             const float* __restrict__ mem1,
                                             const float* __restrict__ mem2,
                                             float* __restrict__ out) {
    int id = blockIdx.x;             // 0..319 == q*80 + b*20 + f
    int o  = blockIdx.y;             // 0..19
    int q  = id / 80;
    int rem = id - q * 80;
    int b  = rem / FR;
    int f  = rem - b * FR;
    int bq = b * QQ + q;
    int hi = g_high[bq], lo = g_low[bq];
    int t  = threadIdx.x;

    size_t outoff = ((size_t)id * OBJN + o) * DD;
    float4* op = (float4*)(out + outoff);                 // Rp
    float4* on = (float4*)(out + RP_ELEMS + outoff);      // Rn
    const float4* pr = (const float4*)(inp + (((size_t)(b * FR + f)) * OBJN + o) * DD);
    float invn = g_invn[(b * FR + f) * OBJN + o];

    if (f != hi && f != lo) {
        #pragma unroll
        for (int i = 0; i < 4; i++) {
            float4 v = __ldg(pr + t + i * 256);
            v.x *= invn; v.y *= invn; v.z *= invn; v.w *= invn;
            __stcs(op + t + i * 256, v);
            __stcs(on + t + i * 256, v);
        }
    } else if (f == hi) {
        // Rn <- mem2[sim2 @ low]; Rp <- R
        int s = g_sim[32 + 16 + bq];
        const float4* pm = (const float4*)(mem2 + (size_t)s * (OBJN * DD) + o * DD);
        #pragma unroll
        for (int i = 0; i < 4; i++) {
            float4 v = __ldg(pr + t + i * 256);
            v.x *= invn; v.y *= invn; v.z *= invn; v.w *= invn;
            __stcs(op + t + i * 256, v);
            float4 w = __ldg(pm + t + i * 256);
            __stcs(on + t + i * 256, w);
        }
    } else {
        // f == lo: Rp <- mem1[sim1 @ low]; Rn <- R
        int s = g_sim[16 + bq];
        const float4* pm = (const float4*)(mem1 + (size_t)s * (OBJN * DD) + o * DD);
        #pragma unroll
        for (int i = 0; i < 4; i++) {
            float4 w = __ldg(pm + t + i * 256);
            __stcs(op + t + i * 256, w);
            float4 v = __ldg(pr + t + i * 256);
            v.x *= invn; v.y *= invn; v.z *= invn; v.w *= invn;
            __stcs(on + t + i * 256, v);
        }
    }
}

// ---------------- K6: high_sim / low_sim outputs ----------------------------
__global__ void k_sims(float* __restrict__ out) {
    int t = threadIdx.x;
    if (t < 16) {
        int q = t >> 2, b = t & 3;
        int bq = b * QQ + q;
        out[OUT_HIGH + t] = (float)g_sim[32 + bq];       // sim2 at high row
        out[OUT_LOW  + t] = (float)g_sim[16 + bq];       // sim1 at low row
    }
}

// ---------------- launch -----------------------------------------------------
extern "C" void kernel_launch(void* const* d_in, const int* in_sizes, int n_in,
                              void* d_out, int out_size) {
    const float* qr   = (const float*)d_in[0];   // [4,4,20]
    const float* inp  = (const float*)d_in[1];   // [4,20,20,4096]
    const float* mem1 = (const float*)d_in[2];   // [1000,81920]
    const float* mem2 = (const float*)d_in[3];   // [1000,81920]
    const int*   rnd  = (const int*)d_in[4];     // [4,4,1]
    float* out = (float*)d_out;

    k_idx<<<1, 32>>>(qr, rnd);
    k_rmax<<<80, 256>>>(inp);
    k_memmp<<<dim3(MCNT, 2), 256>>>(mem1, mem2);
    k_scores<<<dim3(8, KSPLIT, 2), 256>>>();
    k_argmax<<<64, 256>>>();
    k_out<<<dim3(320, OBJN), 256>>>(inp, mem1, mem2, out);
    k_sims<<<1, 32>>>(out);
}